// round 12
// baseline (speedup 1.0000x reference)
#include <cuda_runtime.h>

#define BB 2
#define CC 64
#define HH 96
#define WW 192
#define DD 48
#define GG 8
#define HW (HH*WW)
#define NCH 4

// ---------------- scratch (static device globals; no allocation) ----------------
__device__ float g_fln[BB*GG*HW*8];              // [b][g][h][w][c]
__device__ float g_frn[BB*GG*HW*8];              // [b][g][h][w][c]
__device__ float g_base[(size_t)BB*DD*GG*HW];    // [b][d][g][h][w]
__device__ float g_sw2[3*BB*HW];                 // [s][b][hw]
__device__ float g_wpack2[10368];                // [s][kd][kh][gi][kw][g][dup]
__device__ float g_w1pack[65*9*32];              // [ic][tap][oc]
__device__ float g_pmid[(size_t)NCH*BB*32*HW];   // partial conv32 outputs
__device__ float g_bnscale[32];
__device__ float g_bnbias[32];

// ---------------- f32x2 helpers ----------------
typedef unsigned long long ull;
__device__ __forceinline__ ull pk2(float lo, float hi) {
    ull r;
    asm("mov.b64 %0, {%1, %2};" : "=l"(r) : "f"(lo), "f"(hi));
    return r;
}
__device__ __forceinline__ void upk2(float& lo, float& hi, ull v) {
    asm("mov.b64 {%0, %1}, %2;" : "=f"(lo), "=f"(hi) : "l"(v));
}
__device__ __forceinline__ void fma2(ull& d, ull a, ull b) {
    asm("fma.rn.f32x2 %0, %1, %2, %0;" : "+l"(d) : "l"(a), "l"(b));
}

// ---------------- K0: repack weights ----------------
__global__ void k_prep(const float* __restrict__ w_s, const float* __restrict__ w_m,
                       const float* __restrict__ w_l, const float* __restrict__ w_pred1,
                       const float* __restrict__ gamma, const float* __restrict__ beta,
                       const float* __restrict__ mean, const float* __restrict__ var) {
    int tid = blockIdx.x * blockDim.x + threadIdx.x;
    int stride = gridDim.x * blockDim.x;
    // splatted 3d conv weights: dst [s][kd][kh][gi][kw][g][dup]
    for (int i = tid; i < 10368; i += stride) {
        int g  = (i >> 1) & 7;
        int kw = (i >> 4) % 3;
        int gi = (i / 48) & 7;
        int kh = (i / 384) % 3;
        int kd = (i / 1152) % 3;
        int s  = i / 3456;
        const float* w = (s == 0) ? w_s : ((s == 1) ? w_m : w_l);
        g_wpack2[i] = w[(g*8 + gi)*27 + (kd*3 + kh)*3 + kw];
    }
    // pred1 weights: src (oc, ic, kh, kw) -> dst [ic][t][oc]
    for (int i = tid; i < 65*9*32; i += stride) {
        int oc = i & 31;
        int t  = (i >> 5) % 9;
        int ic = i / 288;
        g_w1pack[i] = w_pred1[(oc*65 + ic)*9 + t];
    }
    if (tid < 32) {
        float sc = gamma[tid] * rsqrtf(var[tid] + 1e-5f);
        g_bnscale[tid] = sc;
        g_bnbias[tid]  = beta[tid] - mean[tid]*sc;
    }
}

// ---------------- K1: per-group L2 normalize, transpose to channel-last ----------------
__global__ void k_norm(const float* __restrict__ fl, const float* __restrict__ fr) {
    int idx = blockIdx.x * blockDim.x + threadIdx.x;   // over BB*GG*HW
    if (idx >= BB*GG*HW) return;
    int pix = idx % HW;
    int bg  = idx / HW;
    const float* pl = fl + (size_t)bg*8*HW + pix;
    const float* pr = fr + (size_t)bg*8*HW + pix;
    float vl[8], vr[8];
    float sl = 0.f, sr = 0.f;
#pragma unroll
    for (int c = 0; c < 8; c++) {
        vl[c] = pl[c*HW]; sl += vl[c]*vl[c];
        vr[c] = pr[c*HW]; sr += vr[c]*vr[c];
    }
    float il = 1.0f / fmaxf(sqrtf(sl), 1e-12f);
    float ir = 1.0f / fmaxf(sqrtf(sr), 1e-12f);
    float* ol = g_fln + (size_t)idx*8;
    float* orr = g_frn + (size_t)idx*8;
#pragma unroll
    for (int c = 0; c < 8; c++) { ol[c] = vl[c]*il; orr[c] = vr[c]*ir; }
}

// ---------------- K2: correlation volume ----------------
__global__ void k_corr() {
    int idx = blockIdx.x * blockDim.x + threadIdx.x;
    if (idx >= BB*GG*HW) return;
    int w = idx % WW;
    int rest = idx / WW;
    int h = rest % HH;
    int bg = rest / HH;
    int g = bg & 7, b = bg >> 3;
    const float4* fl4 = (const float4*)(g_fln + (size_t)idx*8);
    float4 a0 = fl4[0], a1 = fl4[1];
    const float inv = 0.35355339059327373f;
    const float* frrow = g_frn + ((size_t)(bg*HH + h)*WW)*8;
    float* op = g_base + ((size_t)b*DD*GG + g)*HW + h*WW + w;
    for (int d = 0; d < DD; d++) {
        float val = 0.f;
        if (w >= d) {
            const float4* f4 = (const float4*)(frrow + (size_t)(w - d)*8);
            float4 b0 = f4[0], b1 = f4[1];
            val = (a0.x*b0.x + a0.y*b0.y + a0.z*b0.z + a0.w*b0.w +
                   a1.x*b1.x + a1.y*b1.y + a1.z*b1.z + a1.w*b1.w) * inv;
        }
        op[(size_t)d*GG*HW] = val;
    }
}

// ---------------- K3a: predictor conv partials (ic-chunked) ----------------
__global__ void __launch_bounds__(192) k_pred_part(const float* __restrict__ feat_l,
                                                   const float* __restrict__ edge) {
    __shared__ __align__(16) float sW[17*9*32];
    int tid = threadIdx.x;
    int h = blockIdx.x % HH;
    int t2 = blockIdx.x / HH;
    int chunk = t2 % NCH;
    int b = t2 / NCH;
    int c0 = (chunk == 0) ? 0 : (17 + 16*(chunk - 1));
    int cn = (chunk == 0) ? 17 : 16;
    for (int i = tid; i < cn*288; i += 192) sW[i] = g_w1pack[c0*288 + i];
    __syncthreads();

    int w = tid;
    ull acc[16];
#pragma unroll
    for (int k = 0; k < 16; k++) acc[k] = 0ull;

    for (int ic2 = 0; ic2 < cn; ic2++) {
        int ic = c0 + ic2;
        const float* xin = (ic < 64) ? (feat_l + (size_t)(b*64 + ic)*HW)
                                     : (edge + (size_t)b*HW);
#pragma unroll
        for (int kh = 0; kh < 3; kh++) {
            int hh = h + kh - 1;
            if ((unsigned)hh >= HH) continue;
#pragma unroll
            for (int kw = 0; kw < 3; kw++) {
                int ww = w + kw - 1;
                if ((unsigned)ww >= WW) continue;
                float xv = xin[hh*WW + ww];
                ull xp = pk2(xv, xv);
                const ulonglong2* wp = (const ulonglong2*)&sW[(ic2*9 + kh*3 + kw)*32];
#pragma unroll
                for (int j = 0; j < 8; j++) {
                    ulonglong2 v = wp[j];
                    fma2(acc[2*j],   v.x, xp);
                    fma2(acc[2*j+1], v.y, xp);
                }
            }
        }
    }
    float* op = g_pmid + (size_t)chunk*(BB*32*HW) + (size_t)(b*32)*HW + h*WW + w;
#pragma unroll
    for (int k = 0; k < 16; k++) {
        float lo, hi; upk2(lo, hi, acc[k]);
        op[(size_t)(2*k)*HW]   = lo;
        op[(size_t)(2*k+1)*HW] = hi;
    }
}

// ---------------- K3b: combine partials + BN + ReLU + 1x1 + softmax ----------------
__global__ void k_pred_fin(const float* __restrict__ w2, const float* __restrict__ b2,
                           const float* __restrict__ temp) {
    int idx = blockIdx.x * blockDim.x + threadIdx.x;
    if (idx >= BB*HW) return;
    int b = idx / HW;
    int pix = idx % HW;
    float l0 = b2[0], l1 = b2[1], l2 = b2[2];
    const float* base = g_pmid + (size_t)(b*32)*HW + pix;
#pragma unroll 4
    for (int o = 0; o < 32; o++) {
        float v = 0.f;
#pragma unroll
        for (int c = 0; c < NCH; c++)
            v += base[(size_t)c*(BB*32*HW) + (size_t)o*HW];
        v = fmaxf(v*g_bnscale[o] + g_bnbias[o], 0.f);
        l0 += __ldg(&w2[o])      * v;
        l1 += __ldg(&w2[32 + o]) * v;
        l2 += __ldg(&w2[64 + o]) * v;
    }
    float t = fmaxf(temp[0], 0.1f);
    l0 /= t; l1 /= t; l2 /= t;
    float m = fmaxf(l0, fmaxf(l1, l2));
    float e0 = expf(l0 - m), e1 = expf(l1 - m), e2 = expf(l2 - m);
    float r = 1.0f / (e0 + e1 + e2);
    g_sw2[0*BB*HW + idx] = e0*r;
    g_sw2[1*BB*HW + idx] = e1*r;
    g_sw2[2*BB*HW + idx] = e2*r;
}

// ---------------- K4: fused 3-scale dilated conv3d + blend + 1x1x1 ----------------
// d-PAIR version: each thread computes outputs (d0, d0+1) for one pixel pair.
// Weights for (s,kd,kh,gi,kw) are shared by both d outputs -> each weight
// LDS.128 feeds 4 fma2 instead of 2 (smem crossbar demand halves vs fma).
__global__ void __launch_bounds__(192) k_fuse(const float* __restrict__ wf,
                                              const float* __restrict__ bfin,
                                              float* __restrict__ out) {
    __shared__ __align__(16) float sWt[10368];   // 41.5 KB splatted weights
    __shared__ __align__(16) float sWf2[512];
    __shared__ float sBf[32];
    int tid = threadIdx.x;
    for (int i = tid; i < 10368; i += 192) sWt[i] = g_wpack2[i];
    for (int i = tid; i < 512; i += 192) sWf2[i] = wf[i >> 1];
    if (tid < 32) sBf[tid] = bfin[tid];
    __syncthreads();

    int lw = tid % 96;
    int dz = tid / 96;          // 0..1 (warp-uniform)
    int w0 = lw * 2;
    int h  = blockIdx.x % HH;
    int bd = blockIdx.x / HH;
    int dq = bd % 12;
    int b  = bd / 12;
    int d0 = dq*4 + dz*2;       // this thread computes d0 and d0+1

    int pix0 = h*WW + w0;
    // softmax blend weights (per-pixel, d-invariant)
    ull q0, q1, q2;
    {
        float2 s0 = *(const float2*)(g_sw2 + 0*BB*HW + (size_t)b*HW + pix0);
        float2 s1 = *(const float2*)(g_sw2 + 1*BB*HW + (size_t)b*HW + pix0);
        float2 s2 = *(const float2*)(g_sw2 + 2*BB*HW + (size_t)b*HW + pix0);
        q0 = pk2(s0.x, s0.y); q1 = pk2(s1.x, s1.y); q2 = pk2(s2.x, s2.y);
    }

    ull fu[2][8];               // blended result per d
#pragma unroll
    for (int p = 0; p < 2; p++)
#pragma unroll
        for (int g = 0; g < 8; g++) fu[p][g] = 0ull;

    const float* bb = g_base + (size_t)b*DD*GG*HW;

#pragma unroll
    for (int s = 0; s < 3; s++) {
        const int dil = 1 << s;
        const int aoff = (s == 2) ? 4 : 2;
        bool aok = (w0 >= aoff);
        bool cok = (w0 + aoff + 1 < WW);
        ull acc[2][8];
#pragma unroll
        for (int p = 0; p < 2; p++)
#pragma unroll
            for (int g = 0; g < 8; g++) acc[p][g] = 0ull;

#pragma unroll 1
        for (int kd = 0; kd < 3; kd++) {
            int dda = d0 + (kd - 1)*dil;     // tap row for output d0
            int ddb = dda + 1;               // tap row for output d0+1
            bool va = (unsigned)dda < DD;
            bool vb = (unsigned)ddb < DD;
            if (!(va | vb)) continue;
#pragma unroll 1
            for (int kh = 0; kh < 3; kh++) {
                int hh = h + (kh - 1)*dil;
                if ((unsigned)hh >= HH) continue;
                const float* rowa = bb + (size_t)dda*GG*HW + hh*WW;
                const float* rowb = rowa + GG*HW;   // ddb = dda+1
                const float* swrow = &sWt[((s*3 + kd)*3 + kh)*384];
#pragma unroll
                for (int gi = 0; gi < 8; gi++) {
                    const float* pa = rowa + gi*HW;
                    const float* pb = rowb + gi*HW;
                    float2 Aa = make_float2(0.f,0.f), Ca = Aa, Ba = Aa;
                    float2 Ab = make_float2(0.f,0.f), Cb = Ab, Bb = Ab;
                    if (va) {
                        Ba = *(const float2*)(pa + w0);
                        if (aok) Aa = *(const float2*)(pa + w0 - aoff);
                        if (cok) Ca = *(const float2*)(pa + w0 + aoff);
                    }
                    if (vb) {
                        Bb = *(const float2*)(pb + w0);
                        if (aok) Ab = *(const float2*)(pb + w0 - aoff);
                        if (cok) Cb = *(const float2*)(pb + w0 + aoff);
                    }
                    ull p0a, p1a, p2a, p0b, p1b, p2b;
                    p1a = pk2(Ba.x, Ba.y);
                    p1b = pk2(Bb.x, Bb.y);
                    if (s == 0) {
                        p0a = pk2(Aa.y, Ba.x); p2a = pk2(Ba.y, Ca.x);
                        p0b = pk2(Ab.y, Bb.x); p2b = pk2(Bb.y, Cb.x);
                    } else {
                        p0a = pk2(Aa.x, Aa.y); p2a = pk2(Ca.x, Ca.y);
                        p0b = pk2(Ab.x, Ab.y); p2b = pk2(Cb.x, Cb.y);
                    }
                    const ulonglong2* wp = (const ulonglong2*)(swrow + gi*48);
#pragma unroll
                    for (int j = 0; j < 4; j++) {        // kw = 0
                        ulonglong2 wv = wp[j];
                        fma2(acc[0][2*j],   wv.x, p0a); fma2(acc[1][2*j],   wv.x, p0b);
                        fma2(acc[0][2*j+1], wv.y, p0a); fma2(acc[1][2*j+1], wv.y, p0b);
                    }
#pragma unroll
                    for (int j = 0; j < 4; j++) {        // kw = 1
                        ulonglong2 wv = wp[4 + j];
                        fma2(acc[0][2*j],   wv.x, p1a); fma2(acc[1][2*j],   wv.x, p1b);
                        fma2(acc[0][2*j+1], wv.y, p1a); fma2(acc[1][2*j+1], wv.y, p1b);
                    }
#pragma unroll
                    for (int j = 0; j < 4; j++) {        // kw = 2
                        ulonglong2 wv = wp[8 + j];
                        fma2(acc[0][2*j],   wv.x, p2a); fma2(acc[1][2*j],   wv.x, p2b);
                        fma2(acc[0][2*j+1], wv.y, p2a); fma2(acc[1][2*j+1], wv.y, p2b);
                    }
                }
            }
        }
        // blend this scale into fu (frees acc for next scale)
        ull qq = (s == 0) ? q0 : ((s == 1) ? q1 : q2);
#pragma unroll
        for (int g = 0; g < 8; g++) {
            fma2(fu[0][g], qq, acc[0][g]);
            fma2(fu[1][g], qq, acc[1][g]);
        }
    }

    // epilogue: 1x1x1 conv to 32 channels for both d outputs
#pragma unroll
    for (int pd = 0; pd < 2; pd++) {
        int d = d0 + pd;
        float* op = out + (((size_t)b*32)*DD + d)*HW + pix0;
#pragma unroll
        for (int o = 0; o < 32; o++) {
            ull a = pk2(sBf[o], sBf[o]);
            const ulonglong2* wo = (const ulonglong2*)&sWf2[o*16];
#pragma unroll
            for (int j = 0; j < 4; j++) {
                ulonglong2 v = wo[j];
                fma2(a, v.x, fu[pd][2*j]);
                fma2(a, v.y, fu[pd][2*j+1]);
            }
            float lo, hi; upk2(lo, hi, a);
            __stcs((float2*)(op + (size_t)o*DD*HW), make_float2(lo, hi));
        }
    }
}

// ---------------- launch ----------------
extern "C" void kernel_launch(void* const* d_in, const int* in_sizes, int n_in,
                              void* d_out, int out_size) {
    const float* feat_l  = (const float*)d_in[0];
    const float* feat_r  = (const float*)d_in[1];
    const float* edge    = (const float*)d_in[2];
    const float* w_pred1 = (const float*)d_in[3];
    const float* gamma   = (const float*)d_in[4];
    const float* beta    = (const float*)d_in[5];
    const float* mean    = (const float*)d_in[6];
    const float* var     = (const float*)d_in[7];
    const float* w_pred2 = (const float*)d_in[8];
    const float* b_pred2 = (const float*)d_in[9];
    const float* temp    = (const float*)d_in[10];
    const float* w_s     = (const float*)d_in[11];
    const float* w_m     = (const float*)d_in[12];
    const float* w_l     = (const float*)d_in[13];
    const float* w_final = (const float*)d_in[14];
    const float* b_final = (const float*)d_in[15];
    float* out = (float*)d_out;

    k_prep<<<32, 256>>>(w_s, w_m, w_l, w_pred1, gamma, beta, mean, var);
    k_norm<<<(BB*GG*HW + 255)/256, 256>>>(feat_l, feat_r);
    k_corr<<<(BB*GG*HW + 255)/256, 256>>>();
    k_pred_part<<<BB*HH*NCH, 192>>>(feat_l, edge);
    k_pred_fin<<<(BB*HW + 255)/256, 256>>>(w_pred2, b_pred2, temp);
    k_fuse<<<BB*12*HH, 192>>>(w_final, b_final, out);
}

// round 13
// speedup vs baseline: 1.8555x; 1.8555x over previous
#include <cuda_runtime.h>

#define BB 2
#define CC 64
#define HH 96
#define WW 192
#define DD 48
#define GG 8
#define HW (HH*WW)
#define NCH 4

// ---------------- scratch (static device globals; no allocation) ----------------
__device__ float g_fln[BB*GG*HW*8];              // [b][g][h][w][c]
__device__ float g_frn[BB*GG*HW*8];              // [b][g][h][w][c]
__device__ float g_base[(size_t)BB*DD*GG*HW];    // [b][d][g][h][w]
__device__ float g_sw2[3*BB*HW];                 // [s][b][hw]
__device__ float g_wpack2[10368];                // [s][kd][kh][gi][kw][g][dup]
__device__ float g_w1pack[65*9*32];              // [ic][tap][oc]
__device__ float g_pmid[(size_t)NCH*BB*32*HW];   // partial conv32 outputs
__device__ float g_bnscale[32];
__device__ float g_bnbias[32];

// ---------------- f32x2 helpers ----------------
typedef unsigned long long ull;
__device__ __forceinline__ ull pk2(float lo, float hi) {
    ull r;
    asm("mov.b64 %0, {%1, %2};" : "=l"(r) : "f"(lo), "f"(hi));
    return r;
}
__device__ __forceinline__ void upk2(float& lo, float& hi, ull v) {
    asm("mov.b64 {%0, %1}, %2;" : "=f"(lo), "=f"(hi) : "l"(v));
}
__device__ __forceinline__ void fma2(ull& d, ull a, ull b) {
    asm("fma.rn.f32x2 %0, %1, %2, %0;" : "+l"(d) : "l"(a), "l"(b));
}

// ---------------- K0: norm (blocks 0..1535) + weight prep (blocks 1536..1589) ----------------
__global__ void __launch_bounds__(192) k_norm_prep(
        const float* __restrict__ fl, const float* __restrict__ fr,
        const float* __restrict__ w_s, const float* __restrict__ w_m,
        const float* __restrict__ w_l, const float* __restrict__ w_pred1,
        const float* __restrict__ gamma, const float* __restrict__ beta,
        const float* __restrict__ mean, const float* __restrict__ var) {
    int blk = blockIdx.x;
    if (blk < 1536) {
        int idx = blk*192 + threadIdx.x;   // over BB*GG*HW exactly
        int pix = idx % HW;
        int bg  = idx / HW;
        const float* pl = fl + (size_t)bg*8*HW + pix;
        const float* pr = fr + (size_t)bg*8*HW + pix;
        float vl[8], vr[8];
        float sl = 0.f, sr = 0.f;
#pragma unroll
        for (int c = 0; c < 8; c++) {
            vl[c] = pl[c*HW]; sl += vl[c]*vl[c];
            vr[c] = pr[c*HW]; sr += vr[c]*vr[c];
        }
        float il = 1.0f / fmaxf(sqrtf(sl), 1e-12f);
        float ir = 1.0f / fmaxf(sqrtf(sr), 1e-12f);
        float* ol = g_fln + (size_t)idx*8;
        float* orr = g_frn + (size_t)idx*8;
#pragma unroll
        for (int c = 0; c < 8; c++) { ol[c] = vl[c]*il; orr[c] = vr[c]*ir; }
    } else {
        int tid = (blk - 1536)*192 + threadIdx.x;   // 0..10367
        // splatted 3d conv weights: dst [s][kd][kh][gi][kw][g][dup]
        {
            int i = tid;
            int g  = (i >> 1) & 7;
            int kw = (i >> 4) % 3;
            int gi = (i / 48) & 7;
            int kh = (i / 384) % 3;
            int kd = (i / 1152) % 3;
            int s  = i / 3456;
            const float* w = (s == 0) ? w_s : ((s == 1) ? w_m : w_l);
            g_wpack2[i] = w[(g*8 + gi)*27 + (kd*3 + kh)*3 + kw];
        }
        // pred1 weights: src (oc, ic, kh, kw) -> dst [ic][t][oc]
        for (int i = tid; i < 65*9*32; i += 10368) {
            int oc = i & 31;
            int t  = (i >> 5) % 9;
            int ic = i / 288;
            g_w1pack[i] = w_pred1[(oc*65 + ic)*9 + t];
        }
        if (tid < 32) {
            float sc = gamma[tid] * rsqrtf(var[tid] + 1e-5f);
            g_bnscale[tid] = sc;
            g_bnbias[tid]  = beta[tid] - mean[tid]*sc;
        }
    }
}

// ---------------- K1: pred_part (blocks 0..767) + corr (blocks 768..2303) ----------------
__global__ void __launch_bounds__(192) k_corr_pred(const float* __restrict__ feat_l,
                                                   const float* __restrict__ edge) {
    __shared__ __align__(16) float sW[17*9*32];
    int blk = blockIdx.x;
    int tid = threadIdx.x;

    if (blk < BB*HH*NCH) {
        // ---- predictor conv partials ----
        int h = blk % HH;
        int t2 = blk / HH;
        int chunk = t2 % NCH;
        int b = t2 / NCH;
        int c0 = (chunk == 0) ? 0 : (17 + 16*(chunk - 1));
        int cn = (chunk == 0) ? 17 : 16;
        for (int i = tid; i < cn*288; i += 192) sW[i] = g_w1pack[c0*288 + i];
        __syncthreads();

        int w = tid;
        ull acc[16];
#pragma unroll
        for (int k = 0; k < 16; k++) acc[k] = 0ull;

        for (int ic2 = 0; ic2 < cn; ic2++) {
            int ic = c0 + ic2;
            const float* xin = (ic < 64) ? (feat_l + (size_t)(b*64 + ic)*HW)
                                         : (edge + (size_t)b*HW);
#pragma unroll
            for (int kh = 0; kh < 3; kh++) {
                int hh = h + kh - 1;
                if ((unsigned)hh >= HH) continue;
#pragma unroll
                for (int kw = 0; kw < 3; kw++) {
                    int ww = w + kw - 1;
                    if ((unsigned)ww >= WW) continue;
                    float xv = xin[hh*WW + ww];
                    ull xp = pk2(xv, xv);
                    const ulonglong2* wp = (const ulonglong2*)&sW[(ic2*9 + kh*3 + kw)*32];
#pragma unroll
                    for (int j = 0; j < 8; j++) {
                        ulonglong2 v = wp[j];
                        fma2(acc[2*j],   v.x, xp);
                        fma2(acc[2*j+1], v.y, xp);
                    }
                }
            }
        }
        float* op = g_pmid + (size_t)chunk*(BB*32*HW) + (size_t)(b*32)*HW + h*WW + w;
#pragma unroll
        for (int k = 0; k < 16; k++) {
            float lo, hi; upk2(lo, hi, acc[k]);
            op[(size_t)(2*k)*HW]   = lo;
            op[(size_t)(2*k+1)*HW] = hi;
        }
    } else {
        // ---- correlation volume ----
        int idx = (blk - BB*HH*NCH)*192 + tid;   // over BB*GG*HW exactly
        int w = idx % WW;
        int rest = idx / WW;
        int h = rest % HH;
        int bg = rest / HH;
        int g = bg & 7, b = bg >> 3;
        const float4* fl4 = (const float4*)(g_fln + (size_t)idx*8);
        float4 a0 = fl4[0], a1 = fl4[1];
        const float inv = 0.35355339059327373f;
        const float* frrow = g_frn + ((size_t)(bg*HH + h)*WW)*8;
        float* op = g_base + ((size_t)b*DD*GG + g)*HW + h*WW + w;
        for (int d = 0; d < DD; d++) {
            float val = 0.f;
            if (w >= d) {
                const float4* f4 = (const float4*)(frrow + (size_t)(w - d)*8);
                float4 b0 = f4[0], b1 = f4[1];
                val = (a0.x*b0.x + a0.y*b0.y + a0.z*b0.z + a0.w*b0.w +
                       a1.x*b1.x + a1.y*b1.y + a1.z*b1.z + a1.w*b1.w) * inv;
            }
            op[(size_t)d*GG*HW] = val;
        }
    }
}

// ---------------- K2: combine partials + BN + ReLU + 1x1 + softmax ----------------
__global__ void k_pred_fin(const float* __restrict__ w2, const float* __restrict__ b2,
                           const float* __restrict__ temp) {
    int idx = blockIdx.x * blockDim.x + threadIdx.x;
    if (idx >= BB*HW) return;
    int b = idx / HW;
    int pix = idx % HW;
    float l0 = b2[0], l1 = b2[1], l2 = b2[2];
    const float* base = g_pmid + (size_t)(b*32)*HW + pix;
#pragma unroll 4
    for (int o = 0; o < 32; o++) {
        float v = 0.f;
#pragma unroll
        for (int c = 0; c < NCH; c++)
            v += base[(size_t)c*(BB*32*HW) + (size_t)o*HW];
        v = fmaxf(v*g_bnscale[o] + g_bnbias[o], 0.f);
        l0 += __ldg(&w2[o])      * v;
        l1 += __ldg(&w2[32 + o]) * v;
        l2 += __ldg(&w2[64 + o]) * v;
    }
    float t = fmaxf(temp[0], 0.1f);
    l0 /= t; l1 /= t; l2 /= t;
    float m = fmaxf(l0, fmaxf(l1, l2));
    float e0 = expf(l0 - m), e1 = expf(l1 - m), e2 = expf(l2 - m);
    float r = 1.0f / (e0 + e1 + e2);
    g_sw2[0*BB*HW + idx] = e0*r;
    g_sw2[1*BB*HW + idx] = e1*r;
    g_sw2[2*BB*HW + idx] = e2*r;
}

// ---------------- K3: fused 3-scale dilated conv3d + blend + 1x1x1 ----------------
// f32x2 lanes = pixel pair (w0, w0+1). For s>=1 the packed operands ARE the raw
// 8-byte aligned loads (read as ull, zero pk2); only s==0 lane-recombines.
__global__ void __launch_bounds__(192) k_fuse(const float* __restrict__ wf,
                                              const float* __restrict__ bfin,
                                              float* __restrict__ out) {
    __shared__ __align__(16) float sWt[10368];   // 41.5 KB splatted weights
    __shared__ __align__(16) float sWf2[512];
    __shared__ float sBf[32];
    int tid = threadIdx.x;
    for (int i = tid; i < 10368; i += 192) sWt[i] = g_wpack2[i];
    for (int i = tid; i < 512; i += 192) sWf2[i] = wf[i >> 1];
    if (tid < 32) sBf[tid] = bfin[tid];
    __syncthreads();

    int lw = tid % 96;
    int dz = tid / 96;          // 0..1 (warp-uniform)
    int w0 = lw * 2;
    int h  = blockIdx.x % HH;
    int bd = blockIdx.x / HH;
    int d  = (bd % 24)*2 + dz;
    int b  = bd / 24;

    int pix0 = h*WW + w0;
    // softmax blend weights (per-pixel)
    ull q0, q1, q2;
    {
        q0 = *(const ull*)(g_sw2 + 0*BB*HW + (size_t)b*HW + pix0);
        q1 = *(const ull*)(g_sw2 + 1*BB*HW + (size_t)b*HW + pix0);
        q2 = *(const ull*)(g_sw2 + 2*BB*HW + (size_t)b*HW + pix0);
    }

    ull fu[8];
#pragma unroll
    for (int g = 0; g < 8; g++) fu[g] = 0ull;

    const float* bb = g_base + (size_t)b*DD*GG*HW;

#pragma unroll
    for (int s = 0; s < 3; s++) {
        const int dil = 1 << s;
        const int aoff = (s == 2) ? 4 : 2;
        bool aok = (w0 >= aoff);
        bool cok = (w0 + aoff + 1 < WW);
        ull acc[8];
#pragma unroll
        for (int g = 0; g < 8; g++) acc[g] = 0ull;

#pragma unroll 1
        for (int kd = 0; kd < 3; kd++) {
            int dd = d + (kd - 1)*dil;
            if ((unsigned)dd >= DD) continue;
#pragma unroll 1
            for (int kh = 0; kh < 3; kh++) {
                int hh = h + (kh - 1)*dil;
                if ((unsigned)hh >= HH) continue;
                const float* row = bb + (size_t)dd*GG*HW + hh*WW;
                const float* swrow = &sWt[((s*3 + kd)*3 + kh)*384];
#pragma unroll
                for (int gi = 0; gi < 8; gi++) {
                    const float* p = row + gi*HW;
                    ull p0, p1, p2;
                    if (s == 0) {
                        float2 Bv = *(const float2*)(p + w0);
                        float av = aok ? p[w0 - 1] : 0.f;
                        float cv = cok ? p[w0 + 2] : 0.f;
                        p0 = pk2(av, Bv.x);
                        p1 = pk2(Bv.x, Bv.y);
                        p2 = pk2(Bv.y, cv);
                    } else {
                        p1 = *(const ull*)(p + w0);
                        p0 = aok ? *(const ull*)(p + w0 - aoff) : 0ull;
                        p2 = cok ? *(const ull*)(p + w0 + aoff) : 0ull;
                    }
                    const ulonglong2* wp = (const ulonglong2*)(swrow + gi*48);
#pragma unroll
                    for (int j = 0; j < 4; j++) {        // kw = 0
                        ulonglong2 wv = wp[j];
                        fma2(acc[2*j],   wv.x, p0);
                        fma2(acc[2*j+1], wv.y, p0);
                    }
#pragma unroll
                    for (int j = 0; j < 4; j++) {        // kw = 1
                        ulonglong2 wv = wp[4 + j];
                        fma2(acc[2*j],   wv.x, p1);
                        fma2(acc[2*j+1], wv.y, p1);
                    }
#pragma unroll
                    for (int j = 0; j < 4; j++) {        // kw = 2
                        ulonglong2 wv = wp[8 + j];
                        fma2(acc[2*j],   wv.x, p2);
                        fma2(acc[2*j+1], wv.y, p2);
                    }
                }
            }
        }
        // blend this scale into fu (frees acc for next scale)
        ull qq = (s == 0) ? q0 : ((s == 1) ? q1 : q2);
#pragma unroll
        for (int g = 0; g < 8; g++) fma2(fu[g], qq, acc[g]);
    }

    // epilogue: 1x1x1 conv to 32 channels
    float* op = out + (((size_t)b*32)*DD + d)*HW + pix0;
#pragma unroll
    for (int o = 0; o < 32; o++) {
        ull a = pk2(sBf[o], sBf[o]);
        const ulonglong2* wo = (const ulonglong2*)&sWf2[o*16];
#pragma unroll
        for (int j = 0; j < 4; j++) {
            ulonglong2 v = wo[j];
            fma2(a, v.x, fu[2*j]);
            fma2(a, v.y, fu[2*j+1]);
        }
        float lo, hi; upk2(lo, hi, a);
        __stcs((float2*)(op + (size_t)o*DD*HW), make_float2(lo, hi));
    }
}

// ---------------- launch ----------------
extern "C" void kernel_launch(void* const* d_in, const int* in_sizes, int n_in,
                              void* d_out, int out_size) {
    const float* feat_l  = (const float*)d_in[0];
    const float* feat_r  = (const float*)d_in[1];
    const float* edge    = (const float*)d_in[2];
    const float* w_pred1 = (const float*)d_in[3];
    const float* gamma   = (const float*)d_in[4];
    const float* beta    = (const float*)d_in[5];
    const float* mean    = (const float*)d_in[6];
    const float* var     = (const float*)d_in[7];
    const float* w_pred2 = (const float*)d_in[8];
    const float* b_pred2 = (const float*)d_in[9];
    const float* temp    = (const float*)d_in[10];
    const float* w_s     = (const float*)d_in[11];
    const float* w_m     = (const float*)d_in[12];
    const float* w_l     = (const float*)d_in[13];
    const float* w_final = (const float*)d_in[14];
    const float* b_final = (const float*)d_in[15];
    float* out = (float*)d_out;

    // launch idx 0: norm + weight prep (independent work, same deps)
    k_norm_prep<<<1536 + 54, 192>>>(feat_l, feat_r, w_s, w_m, w_l, w_pred1,
                                    gamma, beta, mean, var);
    // launch idx 1: pred_part + corr (both depend only on idx 0)
    k_corr_pred<<<BB*HH*NCH + 1536, 192>>>(feat_l, edge);
    // launch idx 2: softmax weights
    k_pred_fin<<<(BB*HW + 255)/256, 256>>>(w_pred2, b_pred2, temp);
    // launch idx 3: the big one (ncu capture lands here)
    k_fuse<<<BB*24*HH, 192>>>(w_final, b_final, out);
}

// round 14
// speedup vs baseline: 2.7375x; 1.4753x over previous
#include <cuda_runtime.h>

#define BB 2
#define CC 64
#define HH 96
#define WW 192
#define DD 48
#define GG 8
#define HW (HH*WW)
#define NCH 4

// ---------------- scratch (static device globals; no allocation) ----------------
__device__ float g_fln[BB*GG*HW*8];              // [b][g][h][w][c]
__device__ float g_frn[BB*GG*HW*8];              // [b][g][h][w][c]
__device__ float g_base[(size_t)BB*DD*GG*HW];    // [b][d][g][h][w]
__device__ float g_sw2[3*BB*HW];                 // [s][b][hw]
__device__ float g_wpack2[5184];                 // [s][kd][kh][gi][kw][g] (un-dup)
__device__ float g_w1pack[65*9*32];              // [ic][tap][oc]
__device__ float g_pmid[(size_t)NCH*BB*32*HW];   // partial conv32 outputs
__device__ float g_bnscale[32];
__device__ float g_bnbias[32];

// ---------------- f32x2 helpers ----------------
typedef unsigned long long ull;
__device__ __forceinline__ ull pk2(float lo, float hi) {
    ull r;
    asm("mov.b64 %0, {%1, %2};" : "=l"(r) : "f"(lo), "f"(hi));
    return r;
}
__device__ __forceinline__ void upk2(float& lo, float& hi, ull v) {
    asm("mov.b64 {%0, %1}, %2;" : "=f"(lo), "=f"(hi) : "l"(v));
}
__device__ __forceinline__ void fma2(ull& d, ull a, ull b) {
    asm("fma.rn.f32x2 %0, %1, %2, %0;" : "+l"(d) : "l"(a), "l"(b));
}

// ---------------- K0: norm (blocks 0..1535) + weight prep (blocks 1536..1562) ----------------
__global__ void __launch_bounds__(192) k_norm_prep(
        const float* __restrict__ fl, const float* __restrict__ fr,
        const float* __restrict__ w_s, const float* __restrict__ w_m,
        const float* __restrict__ w_l, const float* __restrict__ w_pred1,
        const float* __restrict__ gamma, const float* __restrict__ beta,
        const float* __restrict__ mean, const float* __restrict__ var) {
    int blk = blockIdx.x;
    if (blk < 1536) {
        int idx = blk*192 + threadIdx.x;   // over BB*GG*HW exactly
        int pix = idx % HW;
        int bg  = idx / HW;
        const float* pl = fl + (size_t)bg*8*HW + pix;
        const float* pr = fr + (size_t)bg*8*HW + pix;
        float vl[8], vr[8];
        float sl = 0.f, sr = 0.f;
#pragma unroll
        for (int c = 0; c < 8; c++) {
            vl[c] = pl[c*HW]; sl += vl[c]*vl[c];
            vr[c] = pr[c*HW]; sr += vr[c]*vr[c];
        }
        float il = 1.0f / fmaxf(sqrtf(sl), 1e-12f);
        float ir = 1.0f / fmaxf(sqrtf(sr), 1e-12f);
        float* ol = g_fln + (size_t)idx*8;
        float* orr = g_frn + (size_t)idx*8;
#pragma unroll
        for (int c = 0; c < 8; c++) { ol[c] = vl[c]*il; orr[c] = vr[c]*ir; }
    } else {
        int tid = (blk - 1536)*192 + threadIdx.x;   // 0..5183
        // un-dup'd 3d conv weights: dst [s][kd][kh][gi][kw][g]
        {
            int i = tid;
            int g  = i & 7;
            int kw = (i >> 3) % 3;
            int gi = (i / 24) & 7;
            int kh = (i / 192) % 3;
            int kd = (i / 576) % 3;
            int s  = i / 1728;
            const float* w = (s == 0) ? w_s : ((s == 1) ? w_m : w_l);
            g_wpack2[i] = w[(g*8 + gi)*27 + (kd*3 + kh)*3 + kw];
        }
        // pred1 weights: src (oc, ic, kh, kw) -> dst [ic][t][oc]
        for (int i = tid; i < 65*9*32; i += 5184) {
            int oc = i & 31;
            int t  = (i >> 5) % 9;
            int ic = i / 288;
            g_w1pack[i] = w_pred1[(oc*65 + ic)*9 + t];
        }
        if (tid < 32) {
            float sc = gamma[tid] * rsqrtf(var[tid] + 1e-5f);
            g_bnscale[tid] = sc;
            g_bnbias[tid]  = beta[tid] - mean[tid]*sc;
        }
    }
}

// ---------------- K1: pred_part (blocks 0..767) + corr (blocks 768..2303) ----------------
__global__ void __launch_bounds__(192) k_corr_pred(const float* __restrict__ feat_l,
                                                   const float* __restrict__ edge) {
    __shared__ __align__(16) float sW[17*9*32];
    int blk = blockIdx.x;
    int tid = threadIdx.x;

    if (blk < BB*HH*NCH) {
        // ---- predictor conv partials ----
        int h = blk % HH;
        int t2 = blk / HH;
        int chunk = t2 % NCH;
        int b = t2 / NCH;
        int c0 = (chunk == 0) ? 0 : (17 + 16*(chunk - 1));
        int cn = (chunk == 0) ? 17 : 16;
        for (int i = tid; i < cn*288; i += 192) sW[i] = g_w1pack[c0*288 + i];
        __syncthreads();

        int w = tid;
        ull acc[16];
#pragma unroll
        for (int k = 0; k < 16; k++) acc[k] = 0ull;

        for (int ic2 = 0; ic2 < cn; ic2++) {
            int ic = c0 + ic2;
            const float* xin = (ic < 64) ? (feat_l + (size_t)(b*64 + ic)*HW)
                                         : (edge + (size_t)b*HW);
#pragma unroll
            for (int kh = 0; kh < 3; kh++) {
                int hh = h + kh - 1;
                if ((unsigned)hh >= HH) continue;
#pragma unroll
                for (int kw = 0; kw < 3; kw++) {
                    int ww = w + kw - 1;
                    if ((unsigned)ww >= WW) continue;
                    float xv = xin[hh*WW + ww];
                    ull xp = pk2(xv, xv);
                    const ulonglong2* wp = (const ulonglong2*)&sW[(ic2*9 + kh*3 + kw)*32];
#pragma unroll
                    for (int j = 0; j < 8; j++) {
                        ulonglong2 v = wp[j];
                        fma2(acc[2*j],   v.x, xp);
                        fma2(acc[2*j+1], v.y, xp);
                    }
                }
            }
        }
        float* op = g_pmid + (size_t)chunk*(BB*32*HW) + (size_t)(b*32)*HW + h*WW + w;
#pragma unroll
        for (int k = 0; k < 16; k++) {
            float lo, hi; upk2(lo, hi, acc[k]);
            op[(size_t)(2*k)*HW]   = lo;
            op[(size_t)(2*k+1)*HW] = hi;
        }
    } else {
        // ---- correlation volume ----
        int idx = (blk - BB*HH*NCH)*192 + tid;   // over BB*GG*HW exactly
        int w = idx % WW;
        int rest = idx / WW;
        int h = rest % HH;
        int bg = rest / HH;
        int g = bg & 7, b = bg >> 3;
        const float4* fl4 = (const float4*)(g_fln + (size_t)idx*8);
        float4 a0 = fl4[0], a1 = fl4[1];
        const float inv = 0.35355339059327373f;
        const float* frrow = g_frn + ((size_t)(bg*HH + h)*WW)*8;
        float* op = g_base + ((size_t)b*DD*GG + g)*HW + h*WW + w;
        for (int d = 0; d < DD; d++) {
            float val = 0.f;
            if (w >= d) {
                const float4* f4 = (const float4*)(frrow + (size_t)(w - d)*8);
                float4 b0 = f4[0], b1 = f4[1];
                val = (a0.x*b0.x + a0.y*b0.y + a0.z*b0.z + a0.w*b0.w +
                       a1.x*b1.x + a1.y*b1.y + a1.z*b1.z + a1.w*b1.w) * inv;
            }
            op[(size_t)d*GG*HW] = val;
        }
    }
}

// ---------------- K2: combine partials + BN + ReLU + 1x1 + softmax ----------------
__global__ void k_pred_fin(const float* __restrict__ w2, const float* __restrict__ b2,
                           const float* __restrict__ temp) {
    int idx = blockIdx.x * blockDim.x + threadIdx.x;
    if (idx >= BB*HW) return;
    int b = idx / HW;
    int pix = idx % HW;
    float l0 = b2[0], l1 = b2[1], l2 = b2[2];
    const float* base = g_pmid + (size_t)(b*32)*HW + pix;
#pragma unroll 4
    for (int o = 0; o < 32; o++) {
        float v = 0.f;
#pragma unroll
        for (int c = 0; c < NCH; c++)
            v += base[(size_t)c*(BB*32*HW) + (size_t)o*HW];
        v = fmaxf(v*g_bnscale[o] + g_bnbias[o], 0.f);
        l0 += __ldg(&w2[o])      * v;
        l1 += __ldg(&w2[32 + o]) * v;
        l2 += __ldg(&w2[64 + o]) * v;
    }
    float t = fmaxf(temp[0], 0.1f);
    l0 /= t; l1 /= t; l2 /= t;
    float m = fmaxf(l0, fmaxf(l1, l2));
    float e0 = expf(l0 - m), e1 = expf(l1 - m), e2 = expf(l2 - m);
    float r = 1.0f / (e0 + e1 + e2);
    g_sw2[0*BB*HW + idx] = e0*r;
    g_sw2[1*BB*HW + idx] = e1*r;
    g_sw2[2*BB*HW + idx] = e2*r;
}

// ---------------- K3: fused 3-scale dilated conv3d + blend + 1x1x1 ----------------
// DUP-SWAP: accumulator lanes = g-pair (per pixel); weight operands load
// UN-duplicated (6 LDS.128/gi instead of 12); data is splat via pk2 (ALU pipe).
// fma2 count unchanged; L1TEX traffic from weights halves.
__global__ void __launch_bounds__(192) k_fuse(const float* __restrict__ wf,
                                              const float* __restrict__ bfin,
                                              float* __restrict__ out) {
    __shared__ __align__(16) float sWt[5184];    // 20.7 KB un-dup weights
    __shared__ __align__(16) float sWf[256];
    __shared__ float sBf[32];
    int tid = threadIdx.x;
    for (int i = tid; i < 5184; i += 192) sWt[i] = g_wpack2[i];
    for (int i = tid; i < 256; i += 192) sWf[i] = wf[i];
    if (tid < 32) sBf[tid] = bfin[tid];
    __syncthreads();

    int lw = tid % 96;
    int dz = tid / 96;          // 0..1 (warp-uniform)
    int w0 = lw * 2;
    int h  = blockIdx.x % HH;
    int bd = blockIdx.x / HH;
    int d  = (bd % 24)*2 + dz;
    int b  = bd / 24;

    int pix0 = h*WW + w0;

    ull fu[2][4];               // [px][gpair]
#pragma unroll
    for (int p = 0; p < 2; p++)
#pragma unroll
        for (int g = 0; g < 4; g++) fu[p][g] = 0ull;

    const float* bb = g_base + (size_t)b*DD*GG*HW;

#pragma unroll
    for (int s = 0; s < 3; s++) {
        const int dil = 1 << s;
        const int aoff = (s == 2) ? 4 : 2;
        bool aok = (w0 >= aoff);
        bool cok = (w0 + aoff + 1 < WW);
        ull acc[2][4];
#pragma unroll
        for (int p = 0; p < 2; p++)
#pragma unroll
            for (int g = 0; g < 4; g++) acc[p][g] = 0ull;

#pragma unroll 1
        for (int kd = 0; kd < 3; kd++) {
            int dd = d + (kd - 1)*dil;
            if ((unsigned)dd >= DD) continue;
#pragma unroll 1
            for (int kh = 0; kh < 3; kh++) {
                int hh = h + (kh - 1)*dil;
                if ((unsigned)hh >= HH) continue;
                const float* row = bb + (size_t)dd*GG*HW + hh*WW;
                const float* swrow = &sWt[((s*3 + kd)*3 + kh)*192];
#pragma unroll
                for (int gi = 0; gi < 8; gi++) {
                    const float* p = row + gi*HW;
                    // data splats: m[kw][px] = (x,x)
                    ull m0a, m0b, m1a, m1b, m2a, m2b;
                    if (s == 0) {
                        float2 Bv = *(const float2*)(p + w0);
                        float av = aok ? p[w0 - 1] : 0.f;
                        float cv = cok ? p[w0 + 2] : 0.f;
                        m0a = pk2(av, av);     m0b = pk2(Bv.x, Bv.x);
                        m1a = m0b;             m1b = pk2(Bv.y, Bv.y);
                        m2a = m1b;             m2b = pk2(cv, cv);
                    } else {
                        ull p1v = *(const ull*)(p + w0);
                        ull p0v = aok ? *(const ull*)(p + w0 - aoff) : 0ull;
                        ull p2v = cok ? *(const ull*)(p + w0 + aoff) : 0ull;
                        float x0, x1;
                        upk2(x0, x1, p0v); m0a = pk2(x0, x0); m0b = pk2(x1, x1);
                        upk2(x0, x1, p1v); m1a = pk2(x0, x0); m1b = pk2(x1, x1);
                        upk2(x0, x1, p2v); m2a = pk2(x0, x0); m2b = pk2(x1, x1);
                    }
                    const ulonglong2* wk = (const ulonglong2*)(swrow + gi*24);
                    {   // kw = 0
                        ulonglong2 wv0 = wk[0], wv1 = wk[1];
                        fma2(acc[0][0], wv0.x, m0a); fma2(acc[1][0], wv0.x, m0b);
                        fma2(acc[0][1], wv0.y, m0a); fma2(acc[1][1], wv0.y, m0b);
                        fma2(acc[0][2], wv1.x, m0a); fma2(acc[1][2], wv1.x, m0b);
                        fma2(acc[0][3], wv1.y, m0a); fma2(acc[1][3], wv1.y, m0b);
                    }
                    {   // kw = 1
                        ulonglong2 wv0 = wk[2], wv1 = wk[3];
                        fma2(acc[0][0], wv0.x, m1a); fma2(acc[1][0], wv0.x, m1b);
                        fma2(acc[0][1], wv0.y, m1a); fma2(acc[1][1], wv0.y, m1b);
                        fma2(acc[0][2], wv1.x, m1a); fma2(acc[1][2], wv1.x, m1b);
                        fma2(acc[0][3], wv1.y, m1a); fma2(acc[1][3], wv1.y, m1b);
                    }
                    {   // kw = 2
                        ulonglong2 wv0 = wk[4], wv1 = wk[5];
                        fma2(acc[0][0], wv0.x, m2a); fma2(acc[1][0], wv0.x, m2b);
                        fma2(acc[0][1], wv0.y, m2a); fma2(acc[1][1], wv0.y, m2b);
                        fma2(acc[0][2], wv1.x, m2a); fma2(acc[1][2], wv1.x, m2b);
                        fma2(acc[0][3], wv1.y, m2a); fma2(acc[1][3], wv1.y, m2b);
                    }
                }
            }
        }
        // blend this scale into fu: per-pixel softmax weight splat
        float2 sv = *(const float2*)(g_sw2 + (size_t)s*BB*HW + (size_t)b*HW + pix0);
        ull qa = pk2(sv.x, sv.x), qb = pk2(sv.y, sv.y);
#pragma unroll
        for (int g = 0; g < 4; g++) {
            fma2(fu[0][g], qa, acc[0][g]);
            fma2(fu[1][g], qb, acc[1][g]);
        }
    }

    // epilogue: 1x1x1 conv to 32 channels (un-dup weights, horizontal add)
    float* op = out + (((size_t)b*32)*DD + d)*HW + pix0;
#pragma unroll
    for (int o = 0; o < 32; o++) {
        const ulonglong2* wo = (const ulonglong2*)&sWf[o*8];
        ulonglong2 wv0 = wo[0], wv1 = wo[1];
        ull a0 = 0ull, a1 = 0ull;
        fma2(a0, wv0.x, fu[0][0]); fma2(a1, wv0.x, fu[1][0]);
        fma2(a0, wv0.y, fu[0][1]); fma2(a1, wv0.y, fu[1][1]);
        fma2(a0, wv1.x, fu[0][2]); fma2(a1, wv1.x, fu[1][2]);
        fma2(a0, wv1.y, fu[0][3]); fma2(a1, wv1.y, fu[1][3]);
        float e0, e1, f0, f1;
        upk2(e0, e1, a0);
        upk2(f0, f1, a1);
        float bias = sBf[o];
        __stcs((float2*)(op + (size_t)o*DD*HW),
               make_float2(bias + e0 + e1, bias + f0 + f1));
    }
}

// ---------------- launch ----------------
extern "C" void kernel_launch(void* const* d_in, const int* in_sizes, int n_in,
                              void* d_out, int out_size) {
    const float* feat_l  = (const float*)d_in[0];
    const float* feat_r  = (const float*)d_in[1];
    const float* edge    = (const float*)d_in[2];
    const float* w_pred1 = (const float*)d_in[3];
    const float* gamma   = (const float*)d_in[4];
    const float* beta    = (const float*)d_in[5];
    const float* mean    = (const float*)d_in[6];
    const float* var     = (const float*)d_in[7];
    const float* w_pred2 = (const float*)d_in[8];
    const float* b_pred2 = (const float*)d_in[9];
    const float* temp    = (const float*)d_in[10];
    const float* w_s     = (const float*)d_in[11];
    const float* w_m     = (const float*)d_in[12];
    const float* w_l     = (const float*)d_in[13];
    const float* w_final = (const float*)d_in[14];
    const float* b_final = (const float*)d_in[15];
    float* out = (float*)d_out;

    // launch idx 0: norm + weight prep
    k_norm_prep<<<1536 + 27, 192>>>(feat_l, feat_r, w_s, w_m, w_l, w_pred1,
                                    gamma, beta, mean, var);
    // launch idx 1: pred_part + corr
    k_corr_pred<<<BB*HH*NCH + 1536, 192>>>(feat_l, edge);
    // launch idx 2: softmax weights
    k_pred_fin<<<(BB*HW + 255)/256, 256>>>(w_pred2, b_pred2, temp);
    // launch idx 3: the big one (ncu capture lands here)
    k_fuse<<<BB*24*HH, 192>>>(w_final, b_final, out);
}